// round 1
// baseline (speedup 1.0000x reference)
#include <cuda_runtime.h>

#define BB 16
#define CIN 256
#define FF 76
#define NPIX (FF*FF)          /* 5776 */
#define NA 3
#define NCLS 80
#define NCH 85
#define KK 50
#define NCELL (BB*NA*NPIX)    /* 277248 */

__device__ int    g_posk[NCELL];
__device__ int2   g_poslist[BB*KK];
__device__ int    g_poscount;
__device__ double g_acc[5];   /* xy, wh, obj, cls, l2 */

__constant__ float c_AW[9] = {1.25f,2.0f,4.125f,3.75f,7.75f,7.375f,14.5f,19.5f,46.625f};
__constant__ float c_AH[9] = {1.625f,3.75f,2.875f,7.625f,5.625f,14.875f,11.25f,24.75f,40.75f};
__constant__ float c_MW[3] = {1.25f,2.0f,4.125f};
__constant__ float c_MH[3] = {1.625f,3.75f,2.875f};

__device__ __forceinline__ float sigf(float x){ return 1.0f/(1.0f + expf(-x)); }

__device__ __forceinline__ float bce1(float p, float t){
    // matches jnp: pc = clip(p, 1e-12, 1-1e-7) in fp32; 1-1e-7 rounds to 0.99999988f
    float pc = fminf(fmaxf(p, 1e-12f), 0.99999988f);
    return -(t*logf(pc) + (1.0f - t)*logf(1.0f - pc));
}

__global__ void k_init(){
    int i = blockIdx.x*blockDim.x + threadIdx.x;
    if (i < NCELL) g_posk[i] = -1;
    if (i < 5)     g_acc[i]  = 0.0;
    if (i == 5)    g_poscount = 0;
}

// One thread per batch image, sequential over k => deterministic last-write-wins
__global__ void k_scatter(const float* __restrict__ labels){
    int b = threadIdx.x;
    if (b >= BB) return;
    for (int k = 0; k < KK; k++){
        const float* L = labels + (b*KK + k)*5;
        float cls=L[0], xc=L[1], yc=L[2], w=L[3], h=L[4];
        bool valid = (cls + xc + yc + w + h) > 0.0f;
        float tx = xc*(float)FF, ty = yc*(float)FF;
        float tw = w *(float)FF, th = h *(float)FF;
        float ta = tw*th;
        float best = -1.0f; int bn = 0;
        #pragma unroll
        for (int a = 0; a < 9; a++){
            float inter = fminf(tw, c_AW[a]) * fminf(th, c_AH[a]);
            float iou = inter / (ta + c_AW[a]*c_AH[a] - inter);
            if (iou > best){ best = iou; bn = a; }
        }
        if (valid && bn < 3){
            int ii = (int)tx, jj = (int)ty;
            int cell = ((b*NA + bn)*FF + jj)*FF + ii;
            g_posk[cell] = k;                    // last-wins within this image
            int idx = atomicAdd(&g_poscount, 1);
            g_poslist[idx] = make_int2(cell, k);
        }
    }
}

__global__ void __launch_bounds__(256)
k_main(const float* __restrict__ xin, const float* __restrict__ labels,
       const float* __restrict__ cw,  const float* __restrict__ cb,
       float* __restrict__ dout)
{
    __shared__ float sW[15][CIN];
    __shared__ float sB[15];
    __shared__ float sTx[KK], sTy[KK], sTw[KK], sTh[KK];
    __shared__ float sX1[KK], sY1[KK], sX2[KK], sY2[KK], sAr[KK];
    __shared__ int   sVal[KK];
    __shared__ double red[4][8];

    int tid = threadIdx.x;
    int b   = blockIdx.y;

    // gather the 15 needed conv rows (o = a*85 + ch, ch in 0..4)
    #pragma unroll
    for (int j = 0; j < 15; j++){
        int a = j/5, ch = j%5;
        sW[j][tid] = cw[(a*NCH + ch)*CIN + tid];
    }
    if (tid < 15){ int a = tid/5, ch = tid%5; sB[tid] = cb[a*NCH + ch]; }
    if (tid < KK){
        const float* L = labels + (b*KK + tid)*5;
        float cls=L[0], xc=L[1], yc=L[2], w=L[3], h=L[4];
        sVal[tid] = (cls + xc + yc + w + h) > 0.0f;
        float tx = xc*(float)FF, ty = yc*(float)FF;
        float tw = w *(float)FF, th = h *(float)FF;
        sTx[tid]=tx; sTy[tid]=ty; sTw[tid]=tw; sTh[tid]=th;
        sX1[tid]=tx-tw*0.5f; sY1[tid]=ty-th*0.5f;
        sX2[tid]=tx+tw*0.5f; sY2[tid]=ty+th*0.5f;
        sAr[tid]=tw*th;
    }
    __syncthreads();

    int n = blockIdx.x*blockDim.x + tid;
    double l_xy=0.0, l_wh=0.0, l_obj=0.0, l_l2=0.0;

    if (n < NPIX){
        int h = n / FF, w = n % FF;
        float acc[15];
        #pragma unroll
        for (int j = 0; j < 15; j++) acc[j] = 0.0f;

        const float* xp = xin + (size_t)b*CIN*NPIX + n;
        #pragma unroll 4
        for (int c4 = 0; c4 < CIN/4; c4++){
            float x0 = xp[(size_t)(c4*4+0)*NPIX];
            float x1 = xp[(size_t)(c4*4+1)*NPIX];
            float x2 = xp[(size_t)(c4*4+2)*NPIX];
            float x3 = xp[(size_t)(c4*4+3)*NPIX];
            #pragma unroll
            for (int j = 0; j < 15; j++){
                float4 wq = *reinterpret_cast<const float4*>(&sW[j][c4*4]);
                acc[j] += wq.x*x0;
                acc[j] += wq.y*x1;
                acc[j] += wq.z*x2;
                acc[j] += wq.w*x3;
            }
        }

        float* om = dout + 6;
        #pragma unroll
        for (int a = 0; a < NA; a++){
            float r0 = acc[a*5+0] + sB[a*5+0];
            float r1 = acc[a*5+1] + sB[a*5+1];
            float r2 = acc[a*5+2] + sB[a*5+2];
            float r3 = acc[a*5+3] + sB[a*5+3];
            float r4 = acc[a*5+4] + sB[a*5+4];
            float s0 = sigf(r0), s1 = sigf(r1), s4 = sigf(r4);

            // pred box (grid units)
            float px = s0 + (float)w, py = s1 + (float)h;
            float pw = expf(r2)*c_MW[a], ph = expf(r3)*c_MH[a];
            float px1 = px - pw*0.5f, py1 = py - ph*0.5f;
            float px2 = px + pw*0.5f, py2 = py + ph*0.5f;
            float ap = pw*ph;

            float mx = 0.0f;
            for (int k = 0; k < KK; k++){
                float tlx = fmaxf(px1, sX1[k]), tly = fmaxf(py1, sY1[k]);
                float brx = fminf(px2, sX2[k]), bry = fminf(py2, sY2[k]);
                float inter = (tlx < brx && tly < bry) ? (brx-tlx)*(bry-tly) : 0.0f;
                float iou = inter / (ap + sAr[k] - inter);
                iou = sVal[k] ? iou : 0.0f;
                mx = fmaxf(mx, iou);
            }
            bool ign = mx > 0.7f;

            int cell = ((b*NA + a)*FF + h)*FF + w;
            int k = g_posk[cell];
            bool m = (k >= 0);
            float obj = m ? 1.0f : (ign ? 0.0f : 1.0f);
            float o4 = s4 * obj;
            float* oc = om + (size_t)cell*NCH;

            if (m){
                float tx = sTx[k], ty = sTy[k], tw = sTw[k], th = sTh[k];
                int ii = (int)tx, jj = (int)ty;
                float tfx = tx - (float)ii, tfy = ty - (float)jj;
                float lw = logf(tw / c_MW[a] + 1e-16f);
                float lh = logf(th / c_MH[a] + 1e-16f);
                float sc  = sqrtf(2.0f - tw*th/(float)NPIX);
                float sc2 = sc*sc;
                l_xy += (double)((bce1(s0, tfx) + bce1(s1, tfy)) * sc2);
                float ow2 = r2*sc, ow3 = r3*sc;
                float tw2 = lw*sc, tw3 = lh*sc;
                float d2 = ow2 - tw2, d3 = ow3 - tw3;
                l_wh += 0.5*(double)(d2*d2 + d3*d3);
                l_obj += (double)bce1(o4, 1.0f);
                float e0 = s0 - tfx, e1 = s1 - tfy, e4 = o4 - 1.0f;
                l_l2 += (double)(e0*e0 + e1*e1 + d2*d2 + d3*d3 + e4*e4);
                oc[0]=s0; oc[1]=s1; oc[2]=ow2; oc[3]=ow3; oc[4]=o4;
                // channels 5..84 written by k_pos
            } else {
                l_obj += (double)bce1(o4, 0.0f);  // ==0 exactly when obj==0 (fp32 identity)
                l_l2  += (double)(o4*o4);
                oc[0]=0.0f; oc[1]=0.0f; oc[2]=0.0f; oc[3]=0.0f; oc[4]=o4;
                #pragma unroll
                for (int c5 = 5; c5 < NCH; c5++) oc[c5] = 0.0f;
            }
        }
    }

    // block reduce 4 doubles -> atomicAdd
    int lane = tid & 31, wid = tid >> 5;
    #pragma unroll
    for (int off = 16; off; off >>= 1){
        l_xy  += __shfl_down_sync(0xffffffffu, l_xy,  off);
        l_wh  += __shfl_down_sync(0xffffffffu, l_wh,  off);
        l_obj += __shfl_down_sync(0xffffffffu, l_obj, off);
        l_l2  += __shfl_down_sync(0xffffffffu, l_l2,  off);
    }
    if (lane == 0){ red[0][wid]=l_xy; red[1][wid]=l_wh; red[2][wid]=l_obj; red[3][wid]=l_l2; }
    __syncthreads();
    if (tid == 0){
        double a0=0,a1=0,a2=0,a3=0;
        #pragma unroll
        for (int i = 0; i < 8; i++){ a0+=red[0][i]; a1+=red[1][i]; a2+=red[2][i]; a3+=red[3][i]; }
        atomicAdd(&g_acc[0], a0);
        atomicAdd(&g_acc[1], a1);
        atomicAdd(&g_acc[2], a2);
        atomicAdd(&g_acc[4], a3);
    }
}

// One block per positive cell: 80 class channels (conv dot + bce + l2 + out_m)
__global__ void __launch_bounds__(256)
k_pos(const float* __restrict__ xin, const float* __restrict__ labels,
      const float* __restrict__ cw,  const float* __restrict__ cb,
      float* __restrict__ dout)
{
    __shared__ float  sX[CIN];
    __shared__ double redc[8], redl[8];
    int bi = blockIdx.x;
    if (bi >= g_poscount) return;
    int2 e = g_poslist[bi];
    int cell = e.x, k = e.y;
    if (g_posk[cell] != k) return;   // superseded duplicate

    int w = cell % FF;
    int h = (cell / FF) % FF;
    int a = (cell / NPIX) % NA;
    int b =  cell / (NA*NPIX);
    int n = h*FF + w;

    int tid = threadIdx.x;
    sX[tid] = xin[((size_t)b*CIN + tid)*NPIX + n];
    __syncthreads();

    int cls = (int)labels[(b*KK + k)*5];
    int lane = tid & 31, wid = tid >> 5;
    double lc = 0.0, l2 = 0.0;
    float* oc = dout + 6 + (size_t)cell*NCH;

    for (int i = 0; i < 10; i++){
        int c = wid*10 + i;                 // 8 warps x 10 classes = 80
        int o = a*NCH + 5 + c;
        const float* wr = cw + (size_t)o*CIN;
        float s = 0.0f;
        #pragma unroll
        for (int j = 0; j < 8; j++) s += wr[lane + 32*j] * sX[lane + 32*j];
        #pragma unroll
        for (int off = 16; off; off >>= 1) s += __shfl_down_sync(0xffffffffu, s, off);
        if (lane == 0){
            float raw = s + cb[o];
            float sg = sigf(raw);
            float t = (c == cls) ? 1.0f : 0.0f;
            lc += (double)bce1(sg, t);
            float d = sg - t;
            l2 += (double)(d*d);
            oc[5 + c] = sg;
        }
    }
    if (lane == 0){ redc[wid] = lc; redl[wid] = l2; }
    __syncthreads();
    if (tid == 0){
        double a1=0, a2=0;
        #pragma unroll
        for (int i = 0; i < 8; i++){ a1 += redc[i]; a2 += redl[i]; }
        atomicAdd(&g_acc[3], a1);
        atomicAdd(&g_acc[4], a2);
    }
}

__global__ void k_fin(float* __restrict__ dout){
    double xy=g_acc[0], wh=g_acc[1], ob=g_acc[2], cl=g_acc[3], l2=g_acc[4];
    dout[0] = (float)(xy + wh + ob + cl);
    dout[1] = (float)xy;
    dout[2] = (float)wh;
    dout[3] = (float)ob;
    dout[4] = (float)cl;
    dout[5] = (float)l2;
}

extern "C" void kernel_launch(void* const* d_in, const int* in_sizes, int n_in,
                              void* d_out, int out_size)
{
    const float* xin    = (const float*)d_in[0];
    const float* labels = (const float*)d_in[1];
    const float* cw     = (const float*)d_in[2];
    const float* cb     = (const float*)d_in[3];
    float* dout = (float*)d_out;

    k_init<<<(NCELL + 255)/256, 256>>>();
    k_scatter<<<1, 32>>>(labels);
    dim3 g((NPIX + 255)/256, BB);
    k_main<<<g, 256>>>(xin, labels, cw, cb, dout);
    k_pos<<<BB*KK, 256>>>(xin, labels, cw, cb, dout);
    k_fin<<<1, 1>>>(dout);
}

// round 2
// speedup vs baseline: 1.5556x; 1.5556x over previous
#include <cuda_runtime.h>

#define BB 16
#define CIN 256
#define FF 76
#define NPIX (FF*FF)          /* 5776 */
#define NA 3
#define NCLS 80
#define NCH 85
#define KK 50
#define NCELL (BB*NA*NPIX)    /* 277248 */

__device__ int    g_posk[NCELL];
__device__ int2   g_poslist[BB*KK];
__device__ int    g_poscount;
__device__ double g_acc[5];   /* xy, wh, obj, cls, l2 */

__constant__ float c_AW[9] = {1.25f,2.0f,4.125f,3.75f,7.75f,7.375f,14.5f,19.5f,46.625f};
__constant__ float c_AH[9] = {1.625f,3.75f,2.875f,7.625f,5.625f,14.875f,11.25f,24.75f,40.75f};
__constant__ float c_MW[3] = {1.25f,2.0f,4.125f};
__constant__ float c_MH[3] = {1.625f,3.75f,2.875f};

__device__ __forceinline__ float sigf(float x){ return 1.0f/(1.0f + expf(-x)); }

__device__ __forceinline__ float bce1(float p, float t){
    // matches jnp: pc = clip(p, 1e-12, 1-1e-7) in fp32; 1-1e-7 rounds to 0.99999988f
    float pc = fminf(fmaxf(p, 1e-12f), 0.99999988f);
    return -(t*logf(pc) + (1.0f - t)*logf(1.0f - pc));
}

__global__ void k_init(){
    int i = blockIdx.x*blockDim.x + threadIdx.x;
    if (i < NCELL) g_posk[i] = -1;
    if (i < 5)     g_acc[i]  = 0.0;
    if (i == 5)    g_poscount = 0;
}

// One thread per batch image, sequential over k => deterministic last-write-wins
__global__ void k_scatter(const float* __restrict__ labels){
    int b = threadIdx.x;
    if (b >= BB) return;
    for (int k = 0; k < KK; k++){
        const float* L = labels + (b*KK + k)*5;
        float cls=L[0], xc=L[1], yc=L[2], w=L[3], h=L[4];
        bool valid = (cls + xc + yc + w + h) > 0.0f;
        float tx = xc*(float)FF, ty = yc*(float)FF;
        float tw = w *(float)FF, th = h *(float)FF;
        float ta = tw*th;
        float best = -1.0f; int bn = 0;
        #pragma unroll
        for (int a = 0; a < 9; a++){
            float inter = fminf(tw, c_AW[a]) * fminf(th, c_AH[a]);
            float iou = inter / (ta + c_AW[a]*c_AH[a] - inter);
            if (iou > best){ best = iou; bn = a; }
        }
        if (valid && bn < 3){
            int ii = (int)tx, jj = (int)ty;
            int cell = ((b*NA + bn)*FF + jj)*FF + ii;
            g_posk[cell] = k;                    // last-wins within this image
            int idx = atomicAdd(&g_poscount, 1);
            g_poslist[idx] = make_int2(cell, k);
        }
    }
}

__global__ void __launch_bounds__(256)
k_main(const float* __restrict__ xin, const float* __restrict__ labels,
       const float* __restrict__ cw,  const float* __restrict__ cb,
       float* __restrict__ dout)
{
    __shared__ float sW[15][CIN];
    __shared__ float sB[15];
    __shared__ float sTx[KK], sTy[KK], sTw[KK], sTh[KK];
    __shared__ float sX1[KK], sY1[KK], sX2[KK], sY2[KK], sAr[KK];
    __shared__ int   sVal[KK];
    __shared__ double red[4][8];

    int tid = threadIdx.x;
    int b   = blockIdx.y;
    int n0  = blockIdx.x*256;
    int npb = NPIX - n0; if (npb > 256) npb = 256;

    // ---- coalesced zero pass over this block's 3 output regions ----
    {
        float4 z4 = make_float4(0.f,0.f,0.f,0.f);
        #pragma unroll
        for (int a = 0; a < NA; a++){
            size_t e0 = 6 + ((size_t)((b*NA + a)*NPIX + n0))*NCH;
            float* base = dout + e0;
            int cnt = npb*NCH;
            int pad = (int)((4 - (e0 & 3)) & 3);
            if (pad > cnt) pad = cnt;
            if (tid < pad) base[tid] = 0.0f;
            int nv = (cnt - pad) >> 2;
            float4* b4 = (float4*)(base + pad);
            for (int j = tid; j < nv; j += 256) b4[j] = z4;
            int rem0 = pad + (nv << 2);
            if (rem0 + tid < cnt) base[rem0 + tid] = 0.0f;
        }
    }

    // gather the 15 needed conv rows (o = a*85 + ch, ch in 0..4)
    #pragma unroll
    for (int j = 0; j < 15; j++){
        int a = j/5, ch = j%5;
        sW[j][tid] = cw[(a*NCH + ch)*CIN + tid];
    }
    if (tid < 15){ int a = tid/5, ch = tid%5; sB[tid] = cb[a*NCH + ch]; }
    if (tid < KK){
        const float* L = labels + (b*KK + tid)*5;
        float cls=L[0], xc=L[1], yc=L[2], w=L[3], h=L[4];
        sVal[tid] = (cls + xc + yc + w + h) > 0.0f;
        float tx = xc*(float)FF, ty = yc*(float)FF;
        float tw = w *(float)FF, th = h *(float)FF;
        sTx[tid]=tx; sTy[tid]=ty; sTw[tid]=tw; sTh[tid]=th;
        sX1[tid]=tx-tw*0.5f; sY1[tid]=ty-th*0.5f;
        sX2[tid]=tx+tw*0.5f; sY2[tid]=ty+th*0.5f;
        sAr[tid]=tw*th;
    }
    __syncthreads();   // orders zero-stores before computed stores; publishes sW

    int n = n0 + tid;
    double l_xy=0.0, l_wh=0.0, l_obj=0.0, l_l2=0.0;

    if (n < NPIX){
        int h = n / FF, w = n % FF;
        float acc[15];
        #pragma unroll
        for (int j = 0; j < 15; j++) acc[j] = 0.0f;

        const float* xp = xin + (size_t)b*CIN*NPIX + n;
        #pragma unroll 4
        for (int c4 = 0; c4 < CIN/4; c4++){
            float x0 = xp[(size_t)(c4*4+0)*NPIX];
            float x1 = xp[(size_t)(c4*4+1)*NPIX];
            float x2 = xp[(size_t)(c4*4+2)*NPIX];
            float x3 = xp[(size_t)(c4*4+3)*NPIX];
            #pragma unroll
            for (int j = 0; j < 15; j++){
                float4 wq = *reinterpret_cast<const float4*>(&sW[j][c4*4]);
                acc[j] += wq.x*x0;
                acc[j] += wq.y*x1;
                acc[j] += wq.z*x2;
                acc[j] += wq.w*x3;
            }
        }

        float* om = dout + 6;
        #pragma unroll
        for (int a = 0; a < NA; a++){
            float r0 = acc[a*5+0] + sB[a*5+0];
            float r1 = acc[a*5+1] + sB[a*5+1];
            float r2 = acc[a*5+2] + sB[a*5+2];
            float r3 = acc[a*5+3] + sB[a*5+3];
            float r4 = acc[a*5+4] + sB[a*5+4];
            float s0 = sigf(r0), s1 = sigf(r1), s4 = sigf(r4);

            // pred box (grid units)
            float px = s0 + (float)w, py = s1 + (float)h;
            float pw = expf(r2)*c_MW[a], ph = expf(r3)*c_MH[a];
            float px1 = px - pw*0.5f, py1 = py - ph*0.5f;
            float px2 = px + pw*0.5f, py2 = py + ph*0.5f;
            float ap = pw*ph;

            float mx = 0.0f;
            for (int k = 0; k < KK; k++){
                float tlx = fmaxf(px1, sX1[k]), tly = fmaxf(py1, sY1[k]);
                float brx = fminf(px2, sX2[k]), bry = fminf(py2, sY2[k]);
                float inter = (tlx < brx && tly < bry) ? (brx-tlx)*(bry-tly) : 0.0f;
                float iou = inter / (ap + sAr[k] - inter);
                iou = sVal[k] ? iou : 0.0f;
                mx = fmaxf(mx, iou);
            }
            bool ign = mx > 0.7f;

            int cell = ((b*NA + a)*FF + h)*FF + w;
            int k = g_posk[cell];
            bool m = (k >= 0);
            float obj = m ? 1.0f : (ign ? 0.0f : 1.0f);
            float o4 = s4 * obj;
            float* oc = om + (size_t)cell*NCH;

            if (m){
                float tx = sTx[k], ty = sTy[k], tw = sTw[k], th = sTh[k];
                int ii = (int)tx, jj = (int)ty;
                float tfx = tx - (float)ii, tfy = ty - (float)jj;
                float lw = logf(tw / c_MW[a] + 1e-16f);
                float lh = logf(th / c_MH[a] + 1e-16f);
                float sc  = sqrtf(2.0f - tw*th/(float)NPIX);
                float sc2 = sc*sc;
                l_xy += (double)((bce1(s0, tfx) + bce1(s1, tfy)) * sc2);
                float ow2 = r2*sc, ow3 = r3*sc;
                float tw2 = lw*sc, tw3 = lh*sc;
                float d2 = ow2 - tw2, d3 = ow3 - tw3;
                l_wh += 0.5*(double)(d2*d2 + d3*d3);
                l_obj += (double)bce1(o4, 1.0f);
                float e0 = s0 - tfx, e1 = s1 - tfy, e4 = o4 - 1.0f;
                l_l2 += (double)(e0*e0 + e1*e1 + d2*d2 + d3*d3 + e4*e4);
                oc[0]=s0; oc[1]=s1; oc[2]=ow2; oc[3]=ow3; oc[4]=o4;
                // channels 5..84 written by k_pos
            } else {
                l_obj += (double)bce1(o4, 0.0f);  // ==0 exactly when obj==0 (fp32 identity)
                l_l2  += (double)(o4*o4);
                oc[4] = o4;                       // 0..3 and 5..84 already zeroed
            }
        }
    }

    // block reduce 4 doubles -> atomicAdd
    int lane = tid & 31, wid = tid >> 5;
    #pragma unroll
    for (int off = 16; off; off >>= 1){
        l_xy  += __shfl_down_sync(0xffffffffu, l_xy,  off);
        l_wh  += __shfl_down_sync(0xffffffffu, l_wh,  off);
        l_obj += __shfl_down_sync(0xffffffffu, l_obj, off);
        l_l2  += __shfl_down_sync(0xffffffffu, l_l2,  off);
    }
    if (lane == 0){ red[0][wid]=l_xy; red[1][wid]=l_wh; red[2][wid]=l_obj; red[3][wid]=l_l2; }
    __syncthreads();
    if (tid == 0){
        double a0=0,a1=0,a2=0,a3=0;
        #pragma unroll
        for (int i = 0; i < 8; i++){ a0+=red[0][i]; a1+=red[1][i]; a2+=red[2][i]; a3+=red[3][i]; }
        atomicAdd(&g_acc[0], a0);
        atomicAdd(&g_acc[1], a1);
        atomicAdd(&g_acc[2], a2);
        atomicAdd(&g_acc[4], a3);
    }
}

// One block per positive cell: 80 class channels (conv dot + bce + l2 + out_m)
// All 10 classes of a warp accumulate in parallel (80 FFMA+LDG in flight);
// per-class accumulation order and shfl tree unchanged => bit-identical sums.
__global__ void __launch_bounds__(256)
k_pos(const float* __restrict__ xin, const float* __restrict__ labels,
      const float* __restrict__ cw,  const float* __restrict__ cb,
      float* __restrict__ dout)
{
    __shared__ float  sX[CIN];
    __shared__ double redc[8], redl[8];
    int bi = blockIdx.x;
    if (bi >= g_poscount) return;
    int2 e = g_poslist[bi];
    int cell = e.x, k = e.y;
    if (g_posk[cell] != k) return;   // superseded duplicate

    int w = cell % FF;
    int h = (cell / FF) % FF;
    int a = (cell / NPIX) % NA;
    int b =  cell / (NA*NPIX);
    int n = h*FF + w;

    int tid = threadIdx.x;
    sX[tid] = xin[((size_t)b*CIN + tid)*NPIX + n];
    __syncthreads();

    int cls = (int)labels[(b*KK + k)*5];
    int lane = tid & 31, wid = tid >> 5;
    double lc = 0.0, l2 = 0.0;
    float* oc = dout + 6 + (size_t)cell*NCH;

    const float* wbase = cw + (size_t)(a*NCH + 5 + wid*10)*CIN;
    float s[10];
    #pragma unroll
    for (int i = 0; i < 10; i++) s[i] = 0.0f;
    #pragma unroll
    for (int j = 0; j < 8; j++){
        float x = sX[lane + 32*j];
        #pragma unroll
        for (int i = 0; i < 10; i++)
            s[i] += wbase[(size_t)i*CIN + lane + 32*j] * x;
    }
    #pragma unroll
    for (int i = 0; i < 10; i++){
        #pragma unroll
        for (int off = 16; off; off >>= 1)
            s[i] += __shfl_down_sync(0xffffffffu, s[i], off);
    }
    if (lane == 0){
        #pragma unroll
        for (int i = 0; i < 10; i++){
            int c = wid*10 + i;
            int o = a*NCH + 5 + c;
            float raw = s[i] + cb[o];
            float sg = sigf(raw);
            float t = (c == cls) ? 1.0f : 0.0f;
            lc += (double)bce1(sg, t);
            float d = sg - t;
            l2 += (double)(d*d);
            oc[5 + c] = sg;
        }
    }
    if (lane == 0){ redc[wid] = lc; redl[wid] = l2; }
    __syncthreads();
    if (tid == 0){
        double a1=0, a2=0;
        #pragma unroll
        for (int i = 0; i < 8; i++){ a1 += redc[i]; a2 += redl[i]; }
        atomicAdd(&g_acc[3], a1);
        atomicAdd(&g_acc[4], a2);
    }
}

__global__ void k_fin(float* __restrict__ dout){
    double xy=g_acc[0], wh=g_acc[1], ob=g_acc[2], cl=g_acc[3], l2=g_acc[4];
    dout[0] = (float)(xy + wh + ob + cl);
    dout[1] = (float)xy;
    dout[2] = (float)wh;
    dout[3] = (float)ob;
    dout[4] = (float)cl;
    dout[5] = (float)l2;
}

extern "C" void kernel_launch(void* const* d_in, const int* in_sizes, int n_in,
                              void* d_out, int out_size)
{
    const float* xin    = (const float*)d_in[0];
    const float* labels = (const float*)d_in[1];
    const float* cw     = (const float*)d_in[2];
    const float* cb     = (const float*)d_in[3];
    float* dout = (float*)d_out;

    k_init<<<(NCELL + 255)/256, 256>>>();
    k_scatter<<<1, 32>>>(labels);
    dim3 g((NPIX + 255)/256, BB);
    k_main<<<g, 256>>>(xin, labels, cw, cb, dout);
    k_pos<<<BB*KK, 256>>>(xin, labels, cw, cb, dout);
    k_fin<<<1, 1>>>(dout);
}

// round 3
// speedup vs baseline: 2.2720x; 1.4605x over previous
#include <cuda_runtime.h>

#define BB 16
#define CIN 256
#define FF 76
#define NPIX (FF*FF)          /* 5776 */
#define NA 3
#define NCLS 80
#define NCH 85
#define KK 50
#define NCELL (BB*NA*NPIX)    /* 277248 */

__device__ int    g_posk[NCELL];
__device__ int2   g_poslist[BB*KK];
__device__ int    g_poscount;
__device__ double g_acc[5];   /* xy, wh, obj, cls, l2 */

__constant__ float c_AW[9] = {1.25f,2.0f,4.125f,3.75f,7.75f,7.375f,14.5f,19.5f,46.625f};
__constant__ float c_AH[9] = {1.625f,3.75f,2.875f,7.625f,5.625f,14.875f,11.25f,24.75f,40.75f};
__constant__ float c_MW[3] = {1.25f,2.0f,4.125f};
__constant__ float c_MH[3] = {1.625f,3.75f,2.875f};

__device__ __forceinline__ float sigf(float x){ return 1.0f/(1.0f + expf(-x)); }

__device__ __forceinline__ float bce1(float p, float t){
    // matches jnp: pc = clip(p, 1e-12, 1-1e-7) in fp32; 1-1e-7 rounds to 0.99999988f
    float pc = fminf(fmaxf(p, 1e-12f), 0.99999988f);
    return -(t*logf(pc) + (1.0f - t)*logf(1.0f - pc));
}

__global__ void k_init(){
    int i = blockIdx.x*blockDim.x + threadIdx.x;
    if (i < NCELL) g_posk[i] = -1;
    if (i < 5)     g_acc[i]  = 0.0;
    if (i == 5)    g_poscount = 0;
}

// Cooperative label preload, then one serial thread per image => deterministic
__global__ void k_scatter(const float* __restrict__ labels){
    __shared__ float sL[BB*KK*5];
    int tid = threadIdx.x;
    for (int i = tid; i < BB*KK*5; i += 256) sL[i] = labels[i];
    __syncthreads();
    int b = tid;
    if (b >= BB) return;
    for (int k = 0; k < KK; k++){
        const float* L = sL + (b*KK + k)*5;
        float cls=L[0], xc=L[1], yc=L[2], w=L[3], h=L[4];
        bool valid = (cls + xc + yc + w + h) > 0.0f;
        float tx = xc*(float)FF, ty = yc*(float)FF;
        float tw = w *(float)FF, th = h *(float)FF;
        float ta = tw*th;
        float best = -1.0f; int bn = 0;
        #pragma unroll
        for (int a = 0; a < 9; a++){
            float inter = fminf(tw, c_AW[a]) * fminf(th, c_AH[a]);
            float iou = inter / (ta + c_AW[a]*c_AH[a] - inter);
            if (iou > best){ best = iou; bn = a; }
        }
        if (valid && bn < 3){
            int ii = (int)tx, jj = (int)ty;
            int cell = ((b*NA + bn)*FF + jj)*FF + ii;
            g_posk[cell] = k;                    // last-wins within this image
            int idx = atomicAdd(&g_poscount, 1);
            g_poslist[idx] = make_int2(cell, k);
        }
    }
}

__global__ void __launch_bounds__(128)
k_main(const float* __restrict__ xin, const float* __restrict__ labels,
       const float* __restrict__ cw,  const float* __restrict__ cb,
       float* __restrict__ dout)
{
    __shared__ float sW[15][CIN];
    __shared__ float sB[15];
    __shared__ float sTx[KK], sTy[KK], sTw[KK], sTh[KK];
    __shared__ float sX1[KK], sY1[KK], sX2[KK], sY2[KK], sAr[KK];
    __shared__ double red[4][4];

    int tid = threadIdx.x;
    int b   = blockIdx.y;
    int n0  = blockIdx.x*128;
    int npb = NPIX - n0; if (npb > 128) npb = 128;

    // ---- coalesced zero pass over this block's 3 output regions ----
    {
        float4 z4 = make_float4(0.f,0.f,0.f,0.f);
        #pragma unroll
        for (int a = 0; a < NA; a++){
            size_t e0 = 6 + ((size_t)((b*NA + a)*NPIX + n0))*NCH;
            float* base = dout + e0;
            int cnt = npb*NCH;
            int pad = (int)((4 - (e0 & 3)) & 3);
            if (pad > cnt) pad = cnt;
            if (tid < pad) base[tid] = 0.0f;
            int nv = (cnt - pad) >> 2;
            float4* b4 = (float4*)(base + pad);
            for (int j = tid; j < nv; j += 128) b4[j] = z4;
            int rem0 = pad + (nv << 2);
            if (rem0 + tid < cnt) base[rem0 + tid] = 0.0f;
        }
    }

    // gather the 15 needed conv rows (o = a*85 + ch, ch in 0..4)
    #pragma unroll
    for (int j = 0; j < 15; j++){
        int a = j/5, ch = j%5;
        sW[j][tid]       = cw[(a*NCH + ch)*CIN + tid];
        sW[j][tid + 128] = cw[(a*NCH + ch)*CIN + tid + 128];
    }
    if (tid < 15){ int a = tid/5, ch = tid%5; sB[tid] = cb[a*NCH + ch]; }
    if (tid < KK){
        const float* L = labels + (b*KK + tid)*5;
        float cls=L[0], xc=L[1], yc=L[2], w=L[3], h=L[4];
        bool valid = (cls + xc + yc + w + h) > 0.0f;
        float tx = xc*(float)FF, ty = yc*(float)FF;
        float tw = w *(float)FF, th = h *(float)FF;
        sTx[tid]=tx; sTy[tid]=ty; sTw[tid]=tw; sTh[tid]=th;
        if (valid){
            sX1[tid]=tx-tw*0.5f; sY1[tid]=ty-th*0.5f;
            sX2[tid]=tx+tw*0.5f; sY2[tid]=ty+th*0.5f;
            sAr[tid]=tw*th;
        } else {
            // empty box: never intersects -> iou contribution 0, no branch in hot loop
            sX1[tid]= 3.0e38f; sY1[tid]= 3.0e38f;
            sX2[tid]=-3.0e38f; sY2[tid]=-3.0e38f;
            sAr[tid]= 0.0f;
        }
    }
    __syncthreads();   // orders zero-stores before computed stores; publishes sW

    int n = n0 + tid;
    bool v = (tid < npb);
    int nc = v ? n : n0;
    double l_xy=0.0, l_wh=0.0, l_obj=0.0, l_l2=0.0;

    // ---- 15-channel conv with manual prefetch pipeline (no spills) ----
    float acc[15];
    #pragma unroll
    for (int j = 0; j < 15; j++) acc[j] = 0.0f;
    {
        const float* xp = xin + (size_t)b*CIN*NPIX + nc;
        float x0 = xp[0];
        float x1 = xp[(size_t)1*NPIX];
        float x2 = xp[(size_t)2*NPIX];
        float x3 = xp[(size_t)3*NPIX];
        #pragma unroll 1
        for (int c = 0; c < CIN-4; c += 4){
            float y0 = xp[(size_t)(c+4)*NPIX];
            float y1 = xp[(size_t)(c+5)*NPIX];
            float y2 = xp[(size_t)(c+6)*NPIX];
            float y3 = xp[(size_t)(c+7)*NPIX];
            #pragma unroll
            for (int j = 0; j < 15; j++){
                float4 wq = *reinterpret_cast<const float4*>(&sW[j][c]);
                acc[j] += wq.x*x0;
                acc[j] += wq.y*x1;
                acc[j] += wq.z*x2;
                acc[j] += wq.w*x3;
            }
            x0=y0; x1=y1; x2=y2; x3=y3;
        }
        #pragma unroll
        for (int j = 0; j < 15; j++){
            float4 wq = *reinterpret_cast<const float4*>(&sW[j][CIN-4]);
            acc[j] += wq.x*x0;
            acc[j] += wq.y*x1;
            acc[j] += wq.z*x2;
            acc[j] += wq.w*x3;
        }
    }

    if (v){
        int h = n / FF, w = n % FF;

        // decode all 3 anchors up-front
        float s0[3], s1[3], s4[3], r2v[3], r3v[3];
        float bx1[3], by1[3], bx2[3], by2[3], bap[3];
        #pragma unroll
        for (int a = 0; a < NA; a++){
            float r0 = acc[a*5+0] + sB[a*5+0];
            float r1 = acc[a*5+1] + sB[a*5+1];
            float r2 = acc[a*5+2] + sB[a*5+2];
            float r3 = acc[a*5+3] + sB[a*5+3];
            float r4 = acc[a*5+4] + sB[a*5+4];
            s0[a] = sigf(r0); s1[a] = sigf(r1); s4[a] = sigf(r4);
            r2v[a] = r2; r3v[a] = r3;
            float px = s0[a] + (float)w, py = s1[a] + (float)h;
            float pw = expf(r2)*c_MW[a], ph = expf(r3)*c_MH[a];
            bx1[a] = px - pw*0.5f; by1[a] = py - ph*0.5f;
            bx2[a] = px + pw*0.5f; by2[a] = py + ph*0.5f;
            bap[a] = pw*ph;
        }

        // division-free ignore test: any k with inter > 0.7*union
        bool ign[3] = {false,false,false};
        #pragma unroll 2
        for (int k = 0; k < KK; k++){
            float lx1 = sX1[k], ly1 = sY1[k];
            float lx2 = sX2[k], ly2 = sY2[k];
            float ar  = sAr[k];
            #pragma unroll
            for (int a = 0; a < NA; a++){
                float dx = fminf(bx2[a], lx2) - fmaxf(bx1[a], lx1);
                float dy = fminf(by2[a], ly2) - fmaxf(by1[a], ly1);
                float inter = dx*dy;
                bool en = (dx > 0.0f) & (dy > 0.0f);
                float rhs = 0.7f*(bap[a] + ar - inter);
                ign[a] = ign[a] | (en & (inter > rhs));
            }
        }

        float* om = dout + 6;
        #pragma unroll
        for (int a = 0; a < NA; a++){
            int cell = ((b*NA + a)*FF + h)*FF + w;
            int k = g_posk[cell];
            bool m = (k >= 0);
            float obj = m ? 1.0f : (ign[a] ? 0.0f : 1.0f);
            float o4 = s4[a] * obj;
            float* oc = om + (size_t)cell*NCH;

            if (m){
                float tx = sTx[k], ty = sTy[k], tw = sTw[k], th = sTh[k];
                int ii = (int)tx, jj = (int)ty;
                float tfx = tx - (float)ii, tfy = ty - (float)jj;
                float lw = logf(tw / c_MW[a] + 1e-16f);
                float lh = logf(th / c_MH[a] + 1e-16f);
                float sc  = sqrtf(2.0f - tw*th/(float)NPIX);
                float sc2 = sc*sc;
                l_xy += (double)((bce1(s0[a], tfx) + bce1(s1[a], tfy)) * sc2);
                float ow2 = r2v[a]*sc, ow3 = r3v[a]*sc;
                float tw2 = lw*sc, tw3 = lh*sc;
                float d2 = ow2 - tw2, d3 = ow3 - tw3;
                l_wh += 0.5*(double)(d2*d2 + d3*d3);
                l_obj += (double)bce1(o4, 1.0f);
                float e0 = s0[a] - tfx, e1 = s1[a] - tfy, e4 = o4 - 1.0f;
                l_l2 += (double)(e0*e0 + e1*e1 + d2*d2 + d3*d3 + e4*e4);
                oc[0]=s0[a]; oc[1]=s1[a]; oc[2]=ow2; oc[3]=ow3; oc[4]=o4;
                // channels 5..84 written by k_pos
            } else {
                l_obj += (double)bce1(o4, 0.0f);  // ==0 exactly when obj==0 (fp32 identity)
                l_l2  += (double)(o4*o4);
                oc[4] = o4;                       // 0..3 and 5..84 already zeroed
            }
        }
    }

    // block reduce 4 doubles -> atomicAdd
    int lane = tid & 31, wid = tid >> 5;
    #pragma unroll
    for (int off = 16; off; off >>= 1){
        l_xy  += __shfl_down_sync(0xffffffffu, l_xy,  off);
        l_wh  += __shfl_down_sync(0xffffffffu, l_wh,  off);
        l_obj += __shfl_down_sync(0xffffffffu, l_obj, off);
        l_l2  += __shfl_down_sync(0xffffffffu, l_l2,  off);
    }
    if (lane == 0){ red[0][wid]=l_xy; red[1][wid]=l_wh; red[2][wid]=l_obj; red[3][wid]=l_l2; }
    __syncthreads();
    if (tid == 0){
        double a0=0,a1=0,a2=0,a3=0;
        #pragma unroll
        for (int i = 0; i < 4; i++){ a0+=red[0][i]; a1+=red[1][i]; a2+=red[2][i]; a3+=red[3][i]; }
        atomicAdd(&g_acc[0], a0);
        atomicAdd(&g_acc[1], a1);
        atomicAdd(&g_acc[2], a2);
        atomicAdd(&g_acc[4], a3);
    }
}

// One block per positive cell: 80 class channels (conv dot + bce + l2 + out_m)
__global__ void __launch_bounds__(256)
k_pos(const float* __restrict__ xin, const float* __restrict__ labels,
      const float* __restrict__ cw,  const float* __restrict__ cb,
      float* __restrict__ dout)
{
    __shared__ float  sX[CIN];
    __shared__ double redc[8], redl[8];
    int bi = blockIdx.x;
    if (bi >= g_poscount) return;
    int2 e = g_poslist[bi];
    int cell = e.x, k = e.y;
    if (g_posk[cell] != k) return;   // superseded duplicate

    int w = cell % FF;
    int h = (cell / FF) % FF;
    int a = (cell / NPIX) % NA;
    int b =  cell / (NA*NPIX);
    int n = h*FF + w;

    int tid = threadIdx.x;
    sX[tid] = xin[((size_t)b*CIN + tid)*NPIX + n];
    __syncthreads();

    int cls = (int)labels[(b*KK + k)*5];
    int lane = tid & 31, wid = tid >> 5;
    double lc = 0.0, l2 = 0.0;
    float* oc = dout + 6 + (size_t)cell*NCH;

    const float* wbase = cw + (size_t)(a*NCH + 5 + wid*10)*CIN;
    float s[10];
    #pragma unroll
    for (int i = 0; i < 10; i++) s[i] = 0.0f;
    #pragma unroll
    for (int j = 0; j < 8; j++){
        float x = sX[lane + 32*j];
        #pragma unroll
        for (int i = 0; i < 10; i++)
            s[i] += wbase[(size_t)i*CIN + lane + 32*j] * x;
    }
    #pragma unroll
    for (int i = 0; i < 10; i++){
        #pragma unroll
        for (int off = 16; off; off >>= 1)
            s[i] += __shfl_down_sync(0xffffffffu, s[i], off);
    }
    if (lane == 0){
        #pragma unroll
        for (int i = 0; i < 10; i++){
            int c = wid*10 + i;
            int o = a*NCH + 5 + c;
            float raw = s[i] + cb[o];
            float sg = sigf(raw);
            float t = (c == cls) ? 1.0f : 0.0f;
            lc += (double)bce1(sg, t);
            float d = sg - t;
            l2 += (double)(d*d);
            oc[5 + c] = sg;
        }
    }
    if (lane == 0){ redc[wid] = lc; redl[wid] = l2; }
    __syncthreads();
    if (tid == 0){
        double a1=0, a2=0;
        #pragma unroll
        for (int i = 0; i < 8; i++){ a1 += redc[i]; a2 += redl[i]; }
        atomicAdd(&g_acc[3], a1);
        atomicAdd(&g_acc[4], a2);
    }
}

__global__ void k_fin(float* __restrict__ dout){
    double xy=g_acc[0], wh=g_acc[1], ob=g_acc[2], cl=g_acc[3], l2=g_acc[4];
    dout[0] = (float)(xy + wh + ob + cl);
    dout[1] = (float)xy;
    dout[2] = (float)wh;
    dout[3] = (float)ob;
    dout[4] = (float)cl;
    dout[5] = (float)l2;
}

extern "C" void kernel_launch(void* const* d_in, const int* in_sizes, int n_in,
                              void* d_out, int out_size)
{
    const float* xin    = (const float*)d_in[0];
    const float* labels = (const float*)d_in[1];
    const float* cw     = (const float*)d_in[2];
    const float* cb     = (const float*)d_in[3];
    float* dout = (float*)d_out;

    k_init<<<(NCELL + 255)/256, 256>>>();
    k_scatter<<<1, 256>>>(labels);
    dim3 g((NPIX + 127)/128, BB);
    k_main<<<g, 128>>>(xin, labels, cw, cb, dout);
    k_pos<<<BB*KK, 256>>>(xin, labels, cw, cb, dout);
    k_fin<<<1, 1>>>(dout);
}

// round 4
// speedup vs baseline: 3.2137x; 1.4145x over previous
#include <cuda_runtime.h>

#define BB 16
#define CIN 256
#define FF 76
#define NPIX (FF*FF)          /* 5776 */
#define NA 3
#define NCH 85
#define KK 50
#define PXB 256               /* pixels per block (pairs: 128 threads) */
#define TPB 128

typedef unsigned long long ull;

__device__ double g_acc[5];   /* xy, wh, obj, cls, l2 — k_fin re-zeros after read */

__constant__ float c_AW[9] = {1.25f,2.0f,4.125f,3.75f,7.75f,7.375f,14.5f,19.5f,46.625f};
__constant__ float c_AH[9] = {1.625f,3.75f,2.875f,7.625f,5.625f,14.875f,11.25f,24.75f,40.75f};
__constant__ float c_MW[3] = {1.25f,2.0f,4.125f};
__constant__ float c_MH[3] = {1.625f,3.75f,2.875f};

__device__ __forceinline__ float sigf(float x){ return 1.0f/(1.0f + expf(-x)); }

__device__ __forceinline__ float bce1(float p, float t){
    float pc = fminf(fmaxf(p, 1e-12f), 0.99999988f);
    return -(t*logf(pc) + (1.0f - t)*logf(1.0f - pc));
}

__device__ __forceinline__ void fma2(ull& acc, ull a, ull b){
    asm("fma.rn.f32x2 %0, %1, %2, %0;" : "+l"(acc) : "l"(a), "l"(b));
}
__device__ __forceinline__ float2 u2f2(ull v){
    float2 r; asm("mov.b64 {%0, %1}, %2;" : "=f"(r.x), "=f"(r.y) : "l"(v)); return r;
}

__global__ void __launch_bounds__(TPB)
k_main(const float* __restrict__ xin, const float* __restrict__ labels,
       const float* __restrict__ cw,  const float* __restrict__ cb,
       float* __restrict__ dout)
{
    __shared__ ull    sW2[15][CIN];    /* (w,w) broadcast pairs: 30.7 KB */
    __shared__ float  sB[15];
    __shared__ float  sTx[KK], sTy[KK], sTw[KK], sTh[KK];
    __shared__ float  sX1[KK], sY1[KK], sX2[KK], sY2[KK], sAr[KK];
    __shared__ int    sCls[KK];
    __shared__ int    sOwn[NA*PXB];    /* owner label per cell, -1 none */
    __shared__ int    sPos[NA*PXB];    /* packed (cell<<7)|cls */
    __shared__ int    sCnt;
    __shared__ float  sX[CIN];
    __shared__ double red[5][4];

    int tid = threadIdx.x;
    int b   = blockIdx.y;
    int n0  = blockIdx.x*PXB;
    int npb = NPIX - n0; if (npb > PXB) npb = PXB;

    /* ---- coalesced zero pass over this block's 3 output regions ---- */
    {
        float4 z4 = make_float4(0.f,0.f,0.f,0.f);
        #pragma unroll
        for (int a = 0; a < NA; a++){
            size_t e0 = 6 + ((size_t)((b*NA + a)*NPIX + n0))*NCH;
            float* base = dout + e0;
            int cnt = npb*NCH;
            int pad = (int)((4 - (e0 & 3)) & 3);
            if (pad > cnt) pad = cnt;
            if (tid < pad) base[tid] = 0.0f;
            int nv = (cnt - pad) >> 2;
            float4* b4 = (float4*)(base + pad);
            for (int j = tid; j < nv; j += TPB) b4[j] = z4;
            int rem0 = pad + (nv << 2);
            if (rem0 + tid < cnt) base[rem0 + tid] = 0.0f;
        }
    }

    /* ---- smem init ---- */
    for (int i = tid; i < NA*PXB; i += TPB) sOwn[i] = -1;
    if (tid == 0) sCnt = 0;
    __syncthreads();

    /* weights as (w,w) pairs */
    for (int i = tid; i < 15*CIN; i += TPB){
        int j = i >> 8, c = i & 255;
        int a = j/5, ch = j%5;
        float w = cw[(a*NCH + ch)*CIN + c];
        float2 p = make_float2(w, w);
        sW2[j][c] = *reinterpret_cast<ull*>(&p);
    }
    if (tid < 15){ int a = tid/5, ch = tid%5; sB[tid] = cb[a*NCH + ch]; }
    if (tid < KK){
        const float* L = labels + (b*KK + tid)*5;
        float cls=L[0], xc=L[1], yc=L[2], w=L[3], h=L[4];
        bool valid = (cls + xc + yc + w + h) > 0.0f;
        float tx = xc*(float)FF, ty = yc*(float)FF;
        float tw = w *(float)FF, th = h *(float)FF;
        sTx[tid]=tx; sTy[tid]=ty; sTw[tid]=tw; sTh[tid]=th;
        sCls[tid] = (int)cls;
        if (valid){
            sX1[tid]=tx-tw*0.5f; sY1[tid]=ty-th*0.5f;
            sX2[tid]=tx+tw*0.5f; sY2[tid]=ty+th*0.5f;
            sAr[tid]=tw*th;
        } else {
            sX1[tid]= 3.0e38f; sY1[tid]= 3.0e38f;
            sX2[tid]=-3.0e38f; sY2[tid]=-3.0e38f;
            sAr[tid]= 0.0f;
        }
        /* anchor match + in-block scatter; last-write-wins == max k */
        float ta = tw*th;
        float best = -1.0f; int bn = 0;
        #pragma unroll
        for (int a = 0; a < 9; a++){
            float inter = fminf(tw, c_AW[a]) * fminf(th, c_AH[a]);
            float iou = inter / (ta + c_AW[a]*c_AH[a] - inter);
            if (iou > best){ best = iou; bn = a; }
        }
        if (valid && bn < 3){
            int ii = (int)tx, jj = (int)ty;
            int slot = jj*FF + ii - n0;
            if (slot >= 0 && slot < PXB) atomicMax(&sOwn[bn*PXB + slot], tid);
        }
    }
    __syncthreads();

    int nbase = n0 + 2*tid;
    bool v = (nbase < NPIX);      /* npb even -> pair fully valid or fully not */
    int nb = v ? nbase : n0;
    double l_xy=0.0, l_wh=0.0, l_obj=0.0, l_cl=0.0, l_l2=0.0;

    /* ---- 15-channel conv, pixel-paired f32x2, depth-2 prefetch ---- */
    ull acc[15];
    #pragma unroll
    for (int j = 0; j < 15; j++) acc[j] = 0ULL;
    {
        const ull* xq = reinterpret_cast<const ull*>(xin + (size_t)b*CIN*NPIX + nb);
        const int ST = NPIX/2;
        ull xa0=xq[0*ST], xa1=xq[1*ST], xa2=xq[2*ST], xa3=xq[3*ST];
        ull xb0=xq[4*ST], xb1=xq[5*ST], xb2=xq[6*ST], xb3=xq[7*ST];
        #pragma unroll 2
        for (int c = 0; c < CIN; c += 8){
            int cp = (c + 8 < CIN) ? c + 8 : 0;
            ull y0=xq[(size_t)(cp+0)*ST], y1=xq[(size_t)(cp+1)*ST];
            ull y2=xq[(size_t)(cp+2)*ST], y3=xq[(size_t)(cp+3)*ST];
            #pragma unroll
            for (int j = 0; j < 15; j++){
                ulonglong2 wA = *reinterpret_cast<const ulonglong2*>(&sW2[j][c]);
                ulonglong2 wB = *reinterpret_cast<const ulonglong2*>(&sW2[j][c+2]);
                fma2(acc[j], wA.x, xa0); fma2(acc[j], wA.y, xa1);
                fma2(acc[j], wB.x, xa2); fma2(acc[j], wB.y, xa3);
            }
            int cq = (c + 12 < CIN) ? c + 12 : 0;
            ull z0=xq[(size_t)(cq+0)*ST], z1=xq[(size_t)(cq+1)*ST];
            ull z2=xq[(size_t)(cq+2)*ST], z3=xq[(size_t)(cq+3)*ST];
            #pragma unroll
            for (int j = 0; j < 15; j++){
                ulonglong2 wA = *reinterpret_cast<const ulonglong2*>(&sW2[j][c+4]);
                ulonglong2 wB = *reinterpret_cast<const ulonglong2*>(&sW2[j][c+6]);
                fma2(acc[j], wA.x, xb0); fma2(acc[j], wA.y, xb1);
                fma2(acc[j], wB.x, xb2); fma2(acc[j], wB.y, xb3);
            }
            xa0=y0; xa1=y1; xa2=y2; xa3=y3;
            xb0=z0; xb1=z1; xb2=z2; xb3=z3;
        }
    }

    if (v){
        float a2[2][15];
        #pragma unroll
        for (int j = 0; j < 15; j++){ float2 f = u2f2(acc[j]); a2[0][j]=f.x; a2[1][j]=f.y; }

        float s0[2][3], s1v[2][3], s4v[2][3], r2v[2][3], r3v[2][3];
        float bx1[2][3], by1[2][3], bx2[2][3], by2[2][3], bap[2][3];
        int   hh[2], ww[2];
        #pragma unroll
        for (int p = 0; p < 2; p++){
            int n = nbase + p;
            int h = n / FF, w = n % FF;
            hh[p]=h; ww[p]=w;
            #pragma unroll
            for (int a = 0; a < NA; a++){
                float r0 = a2[p][a*5+0] + sB[a*5+0];
                float r1 = a2[p][a*5+1] + sB[a*5+1];
                float r2 = a2[p][a*5+2] + sB[a*5+2];
                float r3 = a2[p][a*5+3] + sB[a*5+3];
                float r4 = a2[p][a*5+4] + sB[a*5+4];
                s0[p][a]=sigf(r0); s1v[p][a]=sigf(r1); s4v[p][a]=sigf(r4);
                r2v[p][a]=r2; r3v[p][a]=r3;
                float px = s0[p][a] + (float)w, py = s1v[p][a] + (float)h;
                float pw = expf(r2)*c_MW[a], ph = expf(r3)*c_MH[a];
                bx1[p][a]=px-pw*0.5f; by1[p][a]=py-ph*0.5f;
                bx2[p][a]=px+pw*0.5f; by2[p][a]=py+ph*0.5f;
                bap[p][a]=pw*ph;
            }
        }

        bool ig[2][3] = {{false,false,false},{false,false,false}};
        #pragma unroll 2
        for (int k = 0; k < KK; k++){
            float lx1=sX1[k], ly1=sY1[k], lx2=sX2[k], ly2=sY2[k], ar=sAr[k];
            #pragma unroll
            for (int p = 0; p < 2; p++)
            #pragma unroll
            for (int a = 0; a < NA; a++){
                float dx = fminf(bx2[p][a], lx2) - fmaxf(bx1[p][a], lx1);
                float dy = fminf(by2[p][a], ly2) - fmaxf(by1[p][a], ly1);
                float inter = dx*dy;
                bool en = (dx > 0.0f) & (dy > 0.0f);
                ig[p][a] = ig[p][a] | (en & (inter > 0.7f*(bap[p][a] + ar - inter)));
            }
        }

        float* om = dout + 6;
        #pragma unroll
        for (int p = 0; p < 2; p++){
            int n = nbase + p;
            #pragma unroll
            for (int a = 0; a < NA; a++){
                int cell = (b*NA + a)*NPIX + n;
                int k = sOwn[a*PXB + (n - n0)];
                bool m = (k >= 0);
                float obj = m ? 1.0f : (ig[p][a] ? 0.0f : 1.0f);
                float o4 = s4v[p][a] * obj;
                float* oc = om + (size_t)cell*NCH;

                if (m){
                    float tx = sTx[k], ty = sTy[k], tw = sTw[k], th = sTh[k];
                    int ii = (int)tx, jj = (int)ty;
                    float tfx = tx - (float)ii, tfy = ty - (float)jj;
                    float lw = logf(tw / c_MW[a] + 1e-16f);
                    float lh = logf(th / c_MH[a] + 1e-16f);
                    float sc  = sqrtf(2.0f - tw*th/(float)NPIX);
                    float sc2 = sc*sc;
                    l_xy += (double)((bce1(s0[p][a], tfx) + bce1(s1v[p][a], tfy)) * sc2);
                    float ow2 = r2v[p][a]*sc, ow3 = r3v[p][a]*sc;
                    float tw2 = lw*sc, tw3 = lh*sc;
                    float d2 = ow2 - tw2, d3 = ow3 - tw3;
                    l_wh += 0.5*(double)(d2*d2 + d3*d3);
                    l_obj += (double)bce1(o4, 1.0f);
                    float e0 = s0[p][a] - tfx, e1 = s1v[p][a] - tfy, e4 = o4 - 1.0f;
                    l_l2 += (double)(e0*e0 + e1*e1 + d2*d2 + d3*d3 + e4*e4);
                    oc[0]=s0[p][a]; oc[1]=s1v[p][a]; oc[2]=ow2; oc[3]=ow3; oc[4]=o4;
                    int idx = atomicAdd(&sCnt, 1);
                    sPos[idx] = (cell << 7) | sCls[k];
                } else {
                    l_obj += (double)bce1(o4, 0.0f);
                    l_l2  += (double)(o4*o4);
                    oc[4] = o4;
                }
            }
        }
        (void)hh; (void)ww;
    }
    __syncthreads();

    /* ---- class pass for positives owned by this block ---- */
    {
        int lane = tid & 31, wid = tid >> 5;
        int cnt = sCnt;
        for (int q = 0; q < cnt; q++){
            int pk   = sPos[q];
            int cell = pk >> 7;
            int cls  = pk & 127;
            int a    = (cell / NPIX) % NA;
            int pix  = cell % NPIX;
            sX[tid]       = xin[((size_t)b*CIN + tid)*NPIX + pix];
            sX[tid + 128] = xin[((size_t)b*CIN + tid + 128)*NPIX + pix];
            __syncthreads();

            const float* wbase = cw + (size_t)(a*NCH + 5 + wid*20)*CIN;
            float s[20];
            #pragma unroll
            for (int i = 0; i < 20; i++) s[i] = 0.0f;
            #pragma unroll
            for (int j = 0; j < 8; j++){
                float x = sX[lane + 32*j];
                #pragma unroll
                for (int i = 0; i < 20; i++)
                    s[i] += wbase[(size_t)i*CIN + lane + 32*j] * x;
            }
            #pragma unroll
            for (int i = 0; i < 20; i++){
                #pragma unroll
                for (int off = 16; off; off >>= 1)
                    s[i] += __shfl_down_sync(0xffffffffu, s[i], off);
            }
            if (lane == 0){
                float* oc = dout + 6 + (size_t)cell*NCH;
                #pragma unroll
                for (int i = 0; i < 20; i++){
                    int c = wid*20 + i;
                    float raw = s[i] + cb[a*NCH + 5 + c];
                    float sg = sigf(raw);
                    float t = (c == cls) ? 1.0f : 0.0f;
                    l_cl += (double)bce1(sg, t);
                    float d = sg - t;
                    l_l2 += (double)(d*d);
                    oc[5 + c] = sg;
                }
            }
            __syncthreads();
        }
    }

    /* ---- block reduce 5 doubles -> atomicAdd ---- */
    int lane = tid & 31, wid = tid >> 5;
    #pragma unroll
    for (int off = 16; off; off >>= 1){
        l_xy  += __shfl_down_sync(0xffffffffu, l_xy,  off);
        l_wh  += __shfl_down_sync(0xffffffffu, l_wh,  off);
        l_obj += __shfl_down_sync(0xffffffffu, l_obj, off);
        l_cl  += __shfl_down_sync(0xffffffffu, l_cl,  off);
        l_l2  += __shfl_down_sync(0xffffffffu, l_l2,  off);
    }
    if (lane == 0){ red[0][wid]=l_xy; red[1][wid]=l_wh; red[2][wid]=l_obj; red[3][wid]=l_cl; red[4][wid]=l_l2; }
    __syncthreads();
    if (tid == 0){
        double a0=0,a1=0,a2=0,a3=0,a4=0;
        #pragma unroll
        for (int i = 0; i < 4; i++){ a0+=red[0][i]; a1+=red[1][i]; a2+=red[2][i]; a3+=red[3][i]; a4+=red[4][i]; }
        atomicAdd(&g_acc[0], a0);
        atomicAdd(&g_acc[1], a1);
        atomicAdd(&g_acc[2], a2);
        atomicAdd(&g_acc[3], a3);
        atomicAdd(&g_acc[4], a4);
    }
}

__global__ void k_fin(float* __restrict__ dout){
    double xy=g_acc[0], wh=g_acc[1], ob=g_acc[2], cl=g_acc[3], l2=g_acc[4];
    dout[0] = (float)(xy + wh + ob + cl);
    dout[1] = (float)xy;
    dout[2] = (float)wh;
    dout[3] = (float)ob;
    dout[4] = (float)cl;
    dout[5] = (float)l2;
    g_acc[0]=0.0; g_acc[1]=0.0; g_acc[2]=0.0; g_acc[3]=0.0; g_acc[4]=0.0;
}

extern "C" void kernel_launch(void* const* d_in, const int* in_sizes, int n_in,
                              void* d_out, int out_size)
{
    const float* xin    = (const float*)d_in[0];
    const float* labels = (const float*)d_in[1];
    const float* cw     = (const float*)d_in[2];
    const float* cb     = (const float*)d_in[3];
    float* dout = (float*)d_out;

    dim3 g((NPIX + PXB - 1)/PXB, BB);   /* 23 x 16 */
    k_main<<<g, TPB>>>(xin, labels, cw, cb, dout);
    k_fin<<<1, 1>>>(dout);
}

// round 5
// speedup vs baseline: 3.5767x; 1.1130x over previous
#include <cuda_runtime.h>

#define BB 16
#define CIN 256
#define FF 76
#define NPIX (FF*FF)          /* 5776 */
#define NA 3
#define NCH 85
#define KK 50
#define PXB 128               /* pixels per block */
#define TPB 128
#define NPAIR (PXB/2)         /* 64 pixel-pairs per block */
#define NBLK ((NPIX + PXB - 1)/PXB)   /* 46 */
#define TOTB (NBLK*BB)                /* 736 */

typedef unsigned long long ull;

__device__ double       g_acc[5];   /* xy, wh, obj, cls, l2 */
__device__ unsigned int g_done;     /* auto-wrapping block ticket */

__constant__ float c_AW[9] = {1.25f,2.0f,4.125f,3.75f,7.75f,7.375f,14.5f,19.5f,46.625f};
__constant__ float c_AH[9] = {1.625f,3.75f,2.875f,7.625f,5.625f,14.875f,11.25f,24.75f,40.75f};
__constant__ float c_MW[3] = {1.25f,2.0f,4.125f};
__constant__ float c_MH[3] = {1.625f,3.75f,2.875f};

__device__ __forceinline__ float sigf(float x){ return 1.0f/(1.0f + expf(-x)); }

__device__ __forceinline__ float bce1(float p, float t){
    float pc = fminf(fmaxf(p, 1e-12f), 0.99999988f);
    return -(t*logf(pc) + (1.0f - t)*logf(1.0f - pc));
}

__device__ __forceinline__ void fma2(ull& acc, ull a, ull b){
    asm("fma.rn.f32x2 %0, %1, %2, %0;" : "+l"(acc) : "l"(a), "l"(b));
}
__device__ __forceinline__ float2 u2f2(ull v){
    float2 r; asm("mov.b64 {%0, %1}, %2;" : "=f"(r.x), "=f"(r.y) : "l"(v)); return r;
}

__global__ void __launch_bounds__(TPB, 5)
k_main(const float* __restrict__ xin, const float* __restrict__ labels,
       const float* __restrict__ cw,  const float* __restrict__ cb,
       float* __restrict__ dout)
{
    __shared__ ull    sW2[15][CIN];      /* (w,w) pairs: 30.7 KB */
    __shared__ ull    sPart[15][NPAIR];  /* half-1 partial sums: 7.7 KB */
    __shared__ float  sB[15];
    __shared__ float  sTx[KK], sTy[KK], sTw[KK], sTh[KK];
    __shared__ float  sX1[KK], sY1[KK], sX2[KK], sY2[KK], sAr[KK];
    __shared__ int    sCls[KK];
    __shared__ int    sOwn[NA*PXB];
    __shared__ int    sPos[KK];          /* packed (cell<<7)|cls, <=50 per image */
    __shared__ int    sCnt;
    __shared__ float  sX[CIN];
    __shared__ double red[5][4];

    int tid = threadIdx.x;
    int b   = blockIdx.y;
    int n0  = blockIdx.x*PXB;
    int npb = NPIX - n0; if (npb > PXB) npb = PXB;   /* 128 or 16, always even */

    /* ---- coalesced zero pass over this block's 3 output regions ---- */
    {
        float4 z4 = make_float4(0.f,0.f,0.f,0.f);
        #pragma unroll
        for (int a = 0; a < NA; a++){
            size_t e0 = 6 + ((size_t)((b*NA + a)*NPIX + n0))*NCH;
            float* base = dout + e0;
            int cnt = npb*NCH;
            int pad = (int)((4 - (e0 & 3)) & 3);
            if (pad > cnt) pad = cnt;
            if (tid < pad) base[tid] = 0.0f;
            int nv = (cnt - pad) >> 2;
            float4* b4 = (float4*)(base + pad);
            for (int j = tid; j < nv; j += TPB) b4[j] = z4;
            int rem0 = pad + (nv << 2);
            if (rem0 + tid < cnt) base[rem0 + tid] = 0.0f;
        }
    }

    for (int i = tid; i < NA*PXB; i += TPB) sOwn[i] = -1;
    if (tid == 0) sCnt = 0;
    __syncthreads();

    /* weights as (w,w) pairs */
    for (int i = tid; i < 15*CIN; i += TPB){
        int j = i >> 8, c = i & 255;
        int a = j/5, ch = j%5;
        float w = cw[(a*NCH + ch)*CIN + c];
        float2 p = make_float2(w, w);
        sW2[j][c] = *reinterpret_cast<ull*>(&p);
    }
    if (tid < 15){ int a = tid/5, ch = tid%5; sB[tid] = cb[a*NCH + ch]; }
    if (tid < KK){
        const float* L = labels + (b*KK + tid)*5;
        float cls=L[0], xc=L[1], yc=L[2], w=L[3], h=L[4];
        bool valid = (cls + xc + yc + w + h) > 0.0f;
        float tx = xc*(float)FF, ty = yc*(float)FF;
        float tw = w *(float)FF, th = h *(float)FF;
        sTx[tid]=tx; sTy[tid]=ty; sTw[tid]=tw; sTh[tid]=th;
        sCls[tid] = (int)cls;
        if (valid){
            sX1[tid]=tx-tw*0.5f; sY1[tid]=ty-th*0.5f;
            sX2[tid]=tx+tw*0.5f; sY2[tid]=ty+th*0.5f;
            sAr[tid]=tw*th;
        } else {
            sX1[tid]= 3.0e38f; sY1[tid]= 3.0e38f;
            sX2[tid]=-3.0e38f; sY2[tid]=-3.0e38f;
            sAr[tid]= 0.0f;
        }
        float ta = tw*th;
        float best = -1.0f; int bn = 0;
        #pragma unroll
        for (int a = 0; a < 9; a++){
            float inter = fminf(tw, c_AW[a]) * fminf(th, c_AH[a]);
            float iou = inter / (ta + c_AW[a]*c_AH[a] - inter);
            if (iou > best){ best = iou; bn = a; }
        }
        if (valid && bn < 3){
            int ii = (int)tx, jj = (int)ty;
            int slot = jj*FF + ii - n0;
            if (slot >= 0 && slot < PXB) atomicMax(&sOwn[bn*PXB + slot], tid);
        }
    }
    __syncthreads();

    int pt   = tid & (NPAIR-1);     /* pair index within block */
    int half = tid >> 6;            /* channel half: 0 -> [0,128), 1 -> [128,256) */
    int nbase = n0 + 2*pt;
    bool pv = (2*pt < npb);
    int nb = pv ? nbase : n0;
    double l_xy=0.0, l_wh=0.0, l_obj=0.0, l_cl=0.0, l_l2=0.0;

    /* ---- 15-ch conv, pixel-paired f32x2, channels split across 2 threads ---- */
    ull acc[15];
    #pragma unroll
    for (int j = 0; j < 15; j++) acc[j] = 0ULL;
    {
        const ull* xq = reinterpret_cast<const ull*>(xin + (size_t)b*CIN*NPIX + nb);
        const int ST = NPIX/2;
        const int c0 = half*128;
        ull xa0=xq[(size_t)(c0+0)*ST], xa1=xq[(size_t)(c0+1)*ST];
        ull xa2=xq[(size_t)(c0+2)*ST], xa3=xq[(size_t)(c0+3)*ST];
        ull xb0=xq[(size_t)(c0+4)*ST], xb1=xq[(size_t)(c0+5)*ST];
        ull xb2=xq[(size_t)(c0+6)*ST], xb3=xq[(size_t)(c0+7)*ST];
        #pragma unroll 2
        for (int c = 0; c < 128; c += 8){
            int cp = (c + 8 < 128) ? c0 + c + 8 : c0;
            ull y0=xq[(size_t)(cp+0)*ST], y1=xq[(size_t)(cp+1)*ST];
            ull y2=xq[(size_t)(cp+2)*ST], y3=xq[(size_t)(cp+3)*ST];
            #pragma unroll
            for (int j = 0; j < 15; j++){
                ulonglong2 wA = *reinterpret_cast<const ulonglong2*>(&sW2[j][c0+c]);
                ulonglong2 wB = *reinterpret_cast<const ulonglong2*>(&sW2[j][c0+c+2]);
                fma2(acc[j], wA.x, xa0); fma2(acc[j], wA.y, xa1);
                fma2(acc[j], wB.x, xa2); fma2(acc[j], wB.y, xa3);
            }
            int cq = (c + 12 < 128) ? c0 + c + 12 : c0;
            ull z0=xq[(size_t)(cq+0)*ST], z1=xq[(size_t)(cq+1)*ST];
            ull z2=xq[(size_t)(cq+2)*ST], z3=xq[(size_t)(cq+3)*ST];
            #pragma unroll
            for (int j = 0; j < 15; j++){
                ulonglong2 wA = *reinterpret_cast<const ulonglong2*>(&sW2[j][c0+c+4]);
                ulonglong2 wB = *reinterpret_cast<const ulonglong2*>(&sW2[j][c0+c+6]);
                fma2(acc[j], wA.x, xb0); fma2(acc[j], wA.y, xb1);
                fma2(acc[j], wB.x, xb2); fma2(acc[j], wB.y, xb3);
            }
            xa0=y0; xa1=y1; xa2=y2; xa3=y3;
            xb0=z0; xb1=z1; xb2=z2; xb3=z3;
        }
    }
    if (half == 1){
        #pragma unroll
        for (int j = 0; j < 15; j++) sPart[j][pt] = acc[j];
    }
    __syncthreads();

    if (half == 0 && pv){
        float a2[2][15];
        #pragma unroll
        for (int j = 0; j < 15; j++){
            float2 f = u2f2(acc[j]);
            float2 g = u2f2(sPart[j][pt]);
            a2[0][j] = f.x + g.x;
            a2[1][j] = f.y + g.y;
        }

        float s0[2][3], s1v[2][3], s4v[2][3], r2v[2][3], r3v[2][3];
        float bx1[2][3], by1[2][3], bx2[2][3], by2[2][3], bap[2][3];
        #pragma unroll
        for (int p = 0; p < 2; p++){
            int n = nbase + p;
            int h = n / FF, w = n % FF;
            #pragma unroll
            for (int a = 0; a < NA; a++){
                float r0 = a2[p][a*5+0] + sB[a*5+0];
                float r1 = a2[p][a*5+1] + sB[a*5+1];
                float r2 = a2[p][a*5+2] + sB[a*5+2];
                float r3 = a2[p][a*5+3] + sB[a*5+3];
                float r4 = a2[p][a*5+4] + sB[a*5+4];
                s0[p][a]=sigf(r0); s1v[p][a]=sigf(r1); s4v[p][a]=sigf(r4);
                r2v[p][a]=r2; r3v[p][a]=r3;
                float px = s0[p][a] + (float)w, py = s1v[p][a] + (float)h;
                float pw = expf(r2)*c_MW[a], ph = expf(r3)*c_MH[a];
                bx1[p][a]=px-pw*0.5f; by1[p][a]=py-ph*0.5f;
                bx2[p][a]=px+pw*0.5f; by2[p][a]=py+ph*0.5f;
                bap[p][a]=pw*ph;
            }
        }

        bool ig[2][3] = {{false,false,false},{false,false,false}};
        #pragma unroll 2
        for (int k = 0; k < KK; k++){
            float lx1=sX1[k], ly1=sY1[k], lx2=sX2[k], ly2=sY2[k], ar=sAr[k];
            #pragma unroll
            for (int p = 0; p < 2; p++)
            #pragma unroll
            for (int a = 0; a < NA; a++){
                float dx = fminf(bx2[p][a], lx2) - fmaxf(bx1[p][a], lx1);
                float dy = fminf(by2[p][a], ly2) - fmaxf(by1[p][a], ly1);
                float inter = dx*dy;
                bool en = (dx > 0.0f) & (dy > 0.0f);
                ig[p][a] = ig[p][a] | (en & (inter > 0.7f*(bap[p][a] + ar - inter)));
            }
        }

        float* om = dout + 6;
        #pragma unroll
        for (int p = 0; p < 2; p++){
            int n = nbase + p;
            #pragma unroll
            for (int a = 0; a < NA; a++){
                int cell = (b*NA + a)*NPIX + n;
                int k = sOwn[a*PXB + (n - n0)];
                bool m = (k >= 0);
                float obj = m ? 1.0f : (ig[p][a] ? 0.0f : 1.0f);
                float o4 = s4v[p][a] * obj;
                float* oc = om + (size_t)cell*NCH;

                if (m){
                    float tx = sTx[k], ty = sTy[k], tw = sTw[k], th = sTh[k];
                    int ii = (int)tx, jj = (int)ty;
                    float tfx = tx - (float)ii, tfy = ty - (float)jj;
                    float lw = logf(tw / c_MW[a] + 1e-16f);
                    float lh = logf(th / c_MH[a] + 1e-16f);
                    float sc  = sqrtf(2.0f - tw*th/(float)NPIX);
                    float sc2 = sc*sc;
                    l_xy += (double)((bce1(s0[p][a], tfx) + bce1(s1v[p][a], tfy)) * sc2);
                    float ow2 = r2v[p][a]*sc, ow3 = r3v[p][a]*sc;
                    float tw2 = lw*sc, tw3 = lh*sc;
                    float d2 = ow2 - tw2, d3 = ow3 - tw3;
                    l_wh += 0.5*(double)(d2*d2 + d3*d3);
                    l_obj += (double)bce1(o4, 1.0f);
                    float e0 = s0[p][a] - tfx, e1 = s1v[p][a] - tfy, e4 = o4 - 1.0f;
                    l_l2 += (double)(e0*e0 + e1*e1 + d2*d2 + d3*d3 + e4*e4);
                    oc[0]=s0[p][a]; oc[1]=s1v[p][a]; oc[2]=ow2; oc[3]=ow3; oc[4]=o4;
                    int idx = atomicAdd(&sCnt, 1);
                    sPos[idx] = (cell << 7) | sCls[k];
                } else {
                    l_obj += (double)bce1(o4, 0.0f);
                    l_l2  += (double)(o4*o4);
                    oc[4] = o4;
                }
            }
        }
    }
    __syncthreads();

    /* ---- class pass for positives owned by this block ---- */
    {
        int lane = tid & 31, wid = tid >> 5;
        int cnt = sCnt;
        for (int q = 0; q < cnt; q++){
            int pk   = sPos[q];
            int cell = pk >> 7;
            int cls  = pk & 127;
            int a    = (cell / NPIX) % NA;
            int pix  = cell % NPIX;
            sX[tid]       = xin[((size_t)b*CIN + tid)*NPIX + pix];
            sX[tid + 128] = xin[((size_t)b*CIN + tid + 128)*NPIX + pix];
            __syncthreads();

            const float* wbase = cw + (size_t)(a*NCH + 5 + wid*20)*CIN;
            float s[20];
            #pragma unroll
            for (int i = 0; i < 20; i++) s[i] = 0.0f;
            #pragma unroll
            for (int j = 0; j < 8; j++){
                float x = sX[lane + 32*j];
                #pragma unroll
                for (int i = 0; i < 20; i++)
                    s[i] += wbase[(size_t)i*CIN + lane + 32*j] * x;
            }
            #pragma unroll
            for (int i = 0; i < 20; i++){
                #pragma unroll
                for (int off = 16; off; off >>= 1)
                    s[i] += __shfl_down_sync(0xffffffffu, s[i], off);
            }
            if (lane == 0){
                float* oc = dout + 6 + (size_t)cell*NCH;
                #pragma unroll
                for (int i = 0; i < 20; i++){
                    int c = wid*20 + i;
                    float raw = s[i] + cb[a*NCH + 5 + c];
                    float sg = sigf(raw);
                    float t = (c == cls) ? 1.0f : 0.0f;
                    l_cl += (double)bce1(sg, t);
                    float d = sg - t;
                    l_l2 += (double)(d*d);
                    oc[5 + c] = sg;
                }
            }
            __syncthreads();
        }
    }

    /* ---- block reduce 5 doubles -> atomicAdd ---- */
    int lane = tid & 31, wid = tid >> 5;
    #pragma unroll
    for (int off = 16; off; off >>= 1){
        l_xy  += __shfl_down_sync(0xffffffffu, l_xy,  off);
        l_wh  += __shfl_down_sync(0xffffffffu, l_wh,  off);
        l_obj += __shfl_down_sync(0xffffffffu, l_obj, off);
        l_cl  += __shfl_down_sync(0xffffffffu, l_cl,  off);
        l_l2  += __shfl_down_sync(0xffffffffu, l_l2,  off);
    }
    if (lane == 0){ red[0][wid]=l_xy; red[1][wid]=l_wh; red[2][wid]=l_obj; red[3][wid]=l_cl; red[4][wid]=l_l2; }
    __syncthreads();
    if (tid == 0){
        double a0=0,a1=0,a2=0,a3=0,a4=0;
        #pragma unroll
        for (int i = 0; i < 4; i++){ a0+=red[0][i]; a1+=red[1][i]; a2+=red[2][i]; a3+=red[3][i]; a4+=red[4][i]; }
        atomicAdd(&g_acc[0], a0);
        atomicAdd(&g_acc[1], a1);
        atomicAdd(&g_acc[2], a2);
        atomicAdd(&g_acc[3], a3);
        atomicAdd(&g_acc[4], a4);

        /* ---- last-block finalization (replaces k_fin) ---- */
        __threadfence();
        unsigned int t = atomicInc(&g_done, TOTB - 1);   /* wraps to 0 on last */
        if (t == TOTB - 1){
            double xy = atomicAdd(&g_acc[0], 0.0);
            double wh = atomicAdd(&g_acc[1], 0.0);
            double ob = atomicAdd(&g_acc[2], 0.0);
            double cl = atomicAdd(&g_acc[3], 0.0);
            double l2 = atomicAdd(&g_acc[4], 0.0);
            dout[0] = (float)(xy + wh + ob + cl);
            dout[1] = (float)xy;
            dout[2] = (float)wh;
            dout[3] = (float)ob;
            dout[4] = (float)cl;
            dout[5] = (float)l2;
            g_acc[0]=0.0; g_acc[1]=0.0; g_acc[2]=0.0; g_acc[3]=0.0; g_acc[4]=0.0;
            __threadfence();
        }
    }
}

extern "C" void kernel_launch(void* const* d_in, const int* in_sizes, int n_in,
                              void* d_out, int out_size)
{
    const float* xin    = (const float*)d_in[0];
    const float* labels = (const float*)d_in[1];
    const float* cw     = (const float*)d_in[2];
    const float* cb     = (const float*)d_in[3];
    float* dout = (float*)d_out;

    dim3 g(NBLK, BB);   /* 46 x 16 = 736 blocks */
    k_main<<<g, TPB>>>(xin, labels, cw, cb, dout);
}